// round 1
// baseline (speedup 1.0000x reference)
#include <cuda_runtime.h>
#include <cuda_bf16.h>

// Problem constants (fixed by setup_inputs): B=16, Q=1000, C=91, T=128
#define BB 16
#define QQ 1000
#define CC 91
#define TT 128

#define QPB 4   // q rows per block

// out[b,q,t] = 5*L1(pred_box[b,q], tgt_box[b,t])
//            + 2*cost_class(sigmoid(logits[b,q,label[b,t]]))
//            - 2*giou(xyxy(pred_box[b,q]), xyxy(tgt_box[b,t]))
__global__ __launch_bounds__(TT * QPB)
void matcher_kernel(const float* __restrict__ logits,    // [B,Q,C]
                    const float* __restrict__ pboxes,    // [B,Q,4] cxcywh
                    const int*   __restrict__ labels,    // [B,T]
                    const float* __restrict__ tboxes,    // [B,T,4] cxcywh
                    float*       __restrict__ out)       // [B,Q,T]
{
    const int b  = blockIdx.y;
    const int q0 = blockIdx.x * QPB;
    const int t  = threadIdx.x;          // 0..127
    const int qy = threadIdx.y;          // 0..QPB-1
    const int q  = q0 + qy;

    __shared__ float s_cc[QPB][CC + 5];  // padded stride 96 (avoids systematic conflicts)

    // ---- class costs for this block's QPB rows: one entry per class ----
    // cost_class = ( ALPHA*u^2*L - (1-ALPHA)*(x+L) ) / (1+u)^2,  u=e^-x, L=log(1+u)
    if (t < CC) {
        const float x = logits[((long)b * QQ + q) * CC + t];
        const float u = __expf(-x);
        const float L = __logf(1.0f + u);
        const float d = __fdividef(1.0f, 1.0f + u);
        const float cc = (0.25f * u * u * L - 0.75f * (x + L)) * d * d;
        s_cc[qy][t] = 2.0f * cc;  // fold COST_CLASS = 2
    }
    __syncthreads();

    // ---- per (q,t) geometry ----
    const float4 pb = ((const float4*)pboxes)[b * QQ + q];   // cx,cy,w,h
    const float4 tb = ((const float4*)tboxes)[b * TT + t];
    const int   lbl = labels[b * TT + t];

    // L1 in cxcywh space
    const float cbbox = fabsf(pb.x - tb.x) + fabsf(pb.y - tb.y)
                      + fabsf(pb.z - tb.z) + fabsf(pb.w - tb.w);

    // xyxy corners
    const float px0 = pb.x - 0.5f * pb.z, px1 = pb.x + 0.5f * pb.z;
    const float py0 = pb.y - 0.5f * pb.w, py1 = pb.y + 0.5f * pb.w;
    const float tx0 = tb.x - 0.5f * tb.z, tx1 = tb.x + 0.5f * tb.z;
    const float ty0 = tb.y - 0.5f * tb.w, ty1 = tb.y + 0.5f * tb.w;

    const float area_p = (px1 - px0) * (py1 - py0);
    const float area_t = (tx1 - tx0) * (ty1 - ty0);

    const float iw = fmaxf(fminf(px1, tx1) - fmaxf(px0, tx0), 0.0f);
    const float ih = fmaxf(fminf(py1, ty1) - fmaxf(py0, ty0), 0.0f);
    const float inter = iw * ih;
    const float uni   = area_p + area_t - inter;

    const float ew = fmaxf(px1, tx1) - fminf(px0, tx0);
    const float eh = fmaxf(py1, ty1) - fminf(py0, ty0);
    const float area_e = ew * eh;

    // giou = inter/uni - (area_e-uni)/area_e, via one reciprocal:
    // r = 1/(uni*area_e); inter/uni = inter*area_e*r ; (area_e-uni)/area_e = (area_e-uni)*uni*r
    const float r    = __fdividef(1.0f, uni * area_e);
    const float giou = inter * area_e * r - (area_e - uni) * uni * r;

    const float cost = 5.0f * cbbox + s_cc[qy][lbl] - 2.0f * giou;

    out[((long)b * QQ + q) * TT + t] = cost;
}

extern "C" void kernel_launch(void* const* d_in, const int* in_sizes, int n_in,
                              void* d_out, int out_size) {
    const float* logits = (const float*)d_in[0];   // [16,1000,91]
    const float* pboxes = (const float*)d_in[1];   // [16,1000,4]
    const int*   labels = (const int*)  d_in[2];   // [16,128]
    const float* tboxes = (const float*)d_in[3];   // [16,128,4]
    float* out = (float*)d_out;                    // [16,1000,128]

    dim3 grid(QQ / QPB, BB);
    dim3 block(TT, QPB);
    matcher_kernel<<<grid, block>>>(logits, pboxes, labels, tboxes, out);
}

// round 4
// speedup vs baseline: 1.2587x; 1.2587x over previous
#include <cuda_runtime.h>
#include <cuda_bf16.h>

// Problem constants: B=16, Q=1000, C=91, T=128
#define BB 16
#define QQ 1000
#define CC 91
#define TT 128
#define NQ 8          // q rows per block (1000 % 8 == 0 -> 125 blocks in x)

__global__ __launch_bounds__(TT)
void matcher_kernel(const float* __restrict__ logits,    // [B,Q,C]
                    const float* __restrict__ pboxes,    // [B,Q,4] cxcywh
                    const int*   __restrict__ labels,    // [B,T]
                    const float* __restrict__ tboxes,    // [B,T,4] cxcywh
                    float*       __restrict__ out)       // [B,Q,T]
{
    const int b  = blockIdx.y;
    const int q0 = blockIdx.x * NQ;
    const int t  = threadIdx.x;          // 0..127

    __shared__ float  s_cc [NQ][CC + 5]; // class cost, stride 96
    __shared__ float4 s_cor[NQ];         // px0, py0, px1, py1
    __shared__ float4 s_aux[NQ];         // px0+px1, py0+py1, px1-px0, py1-py0

    // ---- phase 1a: class costs for NQ q-rows (NQ*91 = 728 entries) ----
    // cost_class = ( a*u^2*L - (1-a)*(x+L) ) / (1+u)^2,  u=e^-x, L=log(1+u)
    #pragma unroll
    for (int i = t; i < NQ * CC; i += TT) {
        const int qi = i / CC;
        const int c  = i - qi * CC;
        const float x = logits[((long)(b * QQ + q0 + qi)) * CC + c];
        const float u = __expf(-x);
        const float L = __logf(1.0f + u);
        const float d = __fdividef(1.0f, 1.0f + u);
        s_cc[qi][c] = 2.0f * (0.25f * u * u * L - 0.75f * (x + L)) * d * d;
    }

    // ---- phase 1b: per-q geometry ----
    if (t < NQ) {
        const float4 pb = ((const float4*)pboxes)[b * QQ + q0 + t];
        const float px0 = pb.x - 0.5f * pb.z, px1 = pb.x + 0.5f * pb.z;
        const float py0 = pb.y - 0.5f * pb.w, py1 = pb.y + 0.5f * pb.w;
        s_cor[t] = make_float4(px0, py0, px1, py1);
        s_aux[t] = make_float4(px0 + px1, py0 + py1, px1 - px0, py1 - py0);
    }
    __syncthreads();

    // ---- tb side: once per thread ----
    const float4 tb = ((const float4*)tboxes)[b * TT + t];
    const int   lbl = labels[b * TT + t];
    const float tx0 = tb.x - 0.5f * tb.z, tx1 = tb.x + 0.5f * tb.z;
    const float ty0 = tb.y - 0.5f * tb.w, ty1 = tb.y + 0.5f * tb.w;
    const float tsx = tx0 + tx1, tsy = ty0 + ty1;
    const float tdx = tx1 - tx0, tdy = ty1 - ty0;
    const float area_t = tdx * tdy;

    float* outp = out + ((long)(b * QQ + q0)) * TT + t;

    #pragma unroll
    for (int qi = 0; qi < NQ; qi++) {
        const float4 c  = s_cor[qi];
        const float4 a  = s_aux[qi];
        const float  cc = s_cc[qi][lbl];

        // L1 in cxcywh space from corner sums/diffs:
        // |dcx| = 0.5|Δ(x0+x1)|, |dw| = |Δ(x1-x0)|   (same for y/h)
        const float l1 = 0.5f * (fabsf(a.x - tsx) + fabsf(a.y - tsy))
                       + fabsf(a.z - tdx) + fabsf(a.w - tdy);

        const float area_p = a.z * a.w;

        const float mnx1 = fminf(c.z, tx1), mxx0 = fmaxf(c.x, tx0);
        const float mny1 = fminf(c.w, ty1), mxy0 = fmaxf(c.y, ty0);
        const float iw = fmaxf(mnx1 - mxx0, 0.0f);
        const float ih = fmaxf(mny1 - mxy0, 0.0f);
        const float inter = iw * ih;
        const float uni   = area_p + area_t - inter;

        const float ew = fmaxf(c.z, tx1) - fminf(c.x, tx0);
        const float eh = fmaxf(c.w, ty1) - fminf(c.y, ty0);
        const float area_e = ew * eh;

        // giou via one reciprocal: r = 1/(uni*area_e)
        const float r    = __fdividef(1.0f, uni * area_e);
        const float giou = inter * area_e * r - (area_e - uni) * uni * r;

        outp[qi * TT] = 5.0f * l1 + cc - 2.0f * giou;
    }
}

extern "C" void kernel_launch(void* const* d_in, const int* in_sizes, int n_in,
                              void* d_out, int out_size) {
    const float* logits = (const float*)d_in[0];   // [16,1000,91]
    const float* pboxes = (const float*)d_in[1];   // [16,1000,4]
    const int*   labels = (const int*)  d_in[2];   // [16,128]
    const float* tboxes = (const float*)d_in[3];   // [16,128,4]
    float* out = (float*)d_out;                    // [16,1000,128]

    dim3 grid(QQ / NQ, BB);
    dim3 block(TT);
    matcher_kernel<<<grid, block>>>(logits, pboxes, labels, tboxes, out);
}

// round 8
// speedup vs baseline: 1.2887x; 1.0238x over previous
#include <cuda_runtime.h>
#include <cuda_bf16.h>

// Problem constants: B=16, Q=1000, C=91, T=128
#define BB 16
#define QQ 1000
#define CC 91
#define TT 128
#define NQT 20        // q rows per block (1000/20 = 50 blocks in x)
#define NQ2 10        // q rows per half-block (qy = 0/1)

__global__ __launch_bounds__(256)
void matcher_kernel(const float* __restrict__ logits,    // [B,Q,C]
                    const float* __restrict__ pboxes,    // [B,Q,4] cxcywh
                    const int*   __restrict__ labels,    // [B,T]
                    const float* __restrict__ tboxes,    // [B,T,4] cxcywh
                    float*       __restrict__ out)       // [B,Q,T]
{
    const int b   = blockIdx.y;
    const int q0  = blockIdx.x * NQT;
    const int tid = threadIdx.x;         // 0..255
    const int t   = tid & (TT - 1);      // 0..127
    const int qy  = tid >> 7;            // 0..1

    __shared__ float s_cc [NQT][CC + 5];   // class cost, stride 96 floats
    __shared__ float s_geo[NQT][12];       // px0,py0,px1,py1, sx,sy,dx,dy, area_p, pad[3]

    // ---- phase 1a: class costs (20*91 = 1820 entries, contiguous LDG span) ----
    // cost_class = ( a*u^2*L - (1-a)*(x+L) ) / (1+u)^2,  u=e^-x, L=log(1+u)
    {
        const float* lg = logits + (long)b * (QQ * CC) + (long)q0 * CC;
        #pragma unroll
        for (int i = tid; i < NQT * CC; i += 256) {
            const int qi = i / CC;
            const int c  = i - qi * CC;
            const float x = lg[i];
            const float u = __expf(-x);
            const float L = __logf(1.0f + u);
            const float d = __fdividef(1.0f, 1.0f + u);
            s_cc[qi][c] = 2.0f * (0.25f * u * u * L - 0.75f * (x + L)) * d * d;
        }
    }

    // ---- phase 1b: per-q geometry ----
    if (tid < NQT) {
        const float4 pb = ((const float4*)pboxes)[b * QQ + q0 + tid];
        const float px0 = pb.x - 0.5f * pb.z, px1 = pb.x + 0.5f * pb.z;
        const float py0 = pb.y - 0.5f * pb.w, py1 = pb.y + 0.5f * pb.w;
        float* g = s_geo[tid];
        g[0] = px0; g[1] = py0; g[2] = px1; g[3] = py1;
        g[4] = px0 + px1; g[5] = py0 + py1;
        g[6] = px1 - px0; g[7] = py1 - py0;
        g[8] = (px1 - px0) * (py1 - py0);   // area_p
    }
    __syncthreads();

    // ---- tb side: once per thread ----
    const float4 tb = ((const float4*)tboxes)[b * TT + t];
    const int   lbl = labels[b * TT + t];
    const float tx0 = tb.x - 0.5f * tb.z, tx1 = tb.x + 0.5f * tb.z;
    const float ty0 = tb.y - 0.5f * tb.w, ty1 = tb.y + 0.5f * tb.w;
    const float tsx = tx0 + tx1, tsy = ty0 + ty1;
    const float tdx = tx1 - tx0, tdy = ty1 - ty0;
    const float area_t = tdx * tdy;

    float* outp = out + ((long)(b * QQ + q0 + qy * NQ2)) * TT + t;

    #pragma unroll
    for (int qi = 0; qi < NQ2; qi++) {
        const int qb = qy * NQ2 + qi;
        const float4 c = *(const float4*)&s_geo[qb][0];   // corners
        const float4 a = *(const float4*)&s_geo[qb][4];   // sx,sy,dx,dy
        const float  area_p = s_geo[qb][8];
        const float  cc = s_cc[qb][lbl];

        // L1 in cxcywh space: |dcx|=0.5|Δ(x0+x1)|, |dw|=|Δ(x1-x0)|
        const float l1 = 0.5f * (fabsf(a.x - tsx) + fabsf(a.y - tsy))
                       + fabsf(a.z - tdx) + fabsf(a.w - tdy);

        const float iw = fmaxf(fminf(c.z, tx1) - fmaxf(c.x, tx0), 0.0f);
        const float ih = fmaxf(fminf(c.w, ty1) - fmaxf(c.y, ty0), 0.0f);
        const float inter = iw * ih;
        const float uni   = area_p + area_t - inter;

        const float ew = fmaxf(c.z, tx1) - fminf(c.x, tx0);
        const float eh = fmaxf(c.w, ty1) - fminf(c.y, ty0);
        const float area_e = ew * eh;

        // giou via one reciprocal: r = 1/(uni*area_e)
        const float r    = __fdividef(1.0f, uni * area_e);
        const float giou = inter * area_e * r - (area_e - uni) * uni * r;

        outp[qi * TT] = 5.0f * l1 + cc - 2.0f * giou;
    }
}

extern "C" void kernel_launch(void* const* d_in, const int* in_sizes, int n_in,
                              void* d_out, int out_size) {
    const float* logits = (const float*)d_in[0];   // [16,1000,91]
    const float* pboxes = (const float*)d_in[1];   // [16,1000,4]
    const int*   labels = (const int*)  d_in[2];   // [16,128]
    const float* tboxes = (const float*)d_in[3];   // [16,128,4]
    float* out = (float*)d_out;                    // [16,1000,128]

    dim3 grid(QQ / NQT, BB);
    dim3 block(256);
    matcher_kernel<<<grid, block>>>(logits, pboxes, labels, tboxes, out);
}